// round 3
// baseline (speedup 1.0000x reference)
#include <cuda_runtime.h>
#include <math.h>

#define BB 4
#define CC 64
#define HH 128
#define WW 128
#define OO 64
#define KK 3
#define K2 9

typedef unsigned long long u64;
#define FMA2(d,a,b,c) asm("fma.rn.f32x2 %0, %1, %2, %3;" : "=l"(d) : "l"(a), "l"(b), "l"(c))
#define DUP2(d,f)     asm("mov.b64 %0, {%1, %1};" : "=l"(d) : "r"(__float_as_uint(f)))
#define LOF(u) __uint_as_float((unsigned)(u))
#define HIF(u) __uint_as_float((unsigned)((u) >> 32))

// ---------------- scratch (device globals; no allocation allowed) ------------
__device__ float g_xT[BB*HH*WW*CC];     // x transposed to (B,H,W,C)   ~16.8MB
__device__ float g_off[BB*HH*WW*18];    // per-pixel packed offsets (9 y, 9 x)
__device__ float g_mm [BB*HH*WW];       // per-pixel modulation mean
__device__ float g_w3 [K2*CC*OO];       // weight reorganized [k][c][o]

// ---------------- kernel 0: NCHW -> NHWC transpose ---------------------------
__global__ void k_transpose(const float* __restrict__ x) {
    int b = blockIdx.x >> 7;        // gridDim.x = B*H = 512
    int h = blockIdx.x & 127;
    __shared__ float tile[CC][WW + 1];
    for (int idx = threadIdx.x; idx < CC * WW; idx += blockDim.x) {
        int c = idx >> 7, w = idx & 127;
        tile[c][w] = x[((b * CC + c) * HH + h) * WW + w];
    }
    __syncthreads();
    for (int idx = threadIdx.x; idx < CC * WW; idx += blockDim.x) {
        int w = idx >> 6, c = idx & 63;
        g_xT[((b * HH + h) * WW + w) * CC + c] = tile[c][w];
    }
}

// ---------------- kernel 1: weight reorg (O,C,3,3) -> [k][c][o] --------------
__global__ void k_wreorg(const float* __restrict__ weight) {
    for (int idx = blockIdx.x * blockDim.x + threadIdx.x; idx < K2 * CC * OO;
         idx += gridDim.x * blockDim.x) {
        int k = idx / (CC * OO);
        int r = idx % (CC * OO);
        int c = r / OO;
        int o = r % OO;
        g_w3[idx] = weight[(o * CC + c) * K2 + k];
    }
}

// ---------------- kernel 2: fused offset(18) + mod(9) 3x3 conv ---------------
// 27 output channels as 14 packed f32x2 accumulators (last high lane = pad).
#define ACCP(vd, wp) do {                                                      \
    const ulonglong2* w2_ = reinterpret_cast<const ulonglong2*>(wp);           \
    ulonglong2 q_;                                                             \
    q_ = w2_[0]; FMA2(acc[0], vd, q_.x, acc[0]); FMA2(acc[1], vd, q_.y, acc[1]); \
    q_ = w2_[1]; FMA2(acc[2], vd, q_.x, acc[2]); FMA2(acc[3], vd, q_.y, acc[3]); \
    q_ = w2_[2]; FMA2(acc[4], vd, q_.x, acc[4]); FMA2(acc[5], vd, q_.y, acc[5]); \
    q_ = w2_[3]; FMA2(acc[6], vd, q_.x, acc[6]); FMA2(acc[7], vd, q_.y, acc[7]); \
    q_ = w2_[4]; FMA2(acc[8], vd, q_.x, acc[8]); FMA2(acc[9], vd, q_.y, acc[9]); \
    q_ = w2_[5]; FMA2(acc[10], vd, q_.x, acc[10]); FMA2(acc[11], vd, q_.y, acc[11]); \
    q_ = w2_[6]; FMA2(acc[12], vd, q_.x, acc[12]); FMA2(acc[13], vd, q_.y, acc[13]); \
} while (0)

__global__ void k_offmod(const float* __restrict__ offset_w,
                         const float* __restrict__ offset_b,
                         const float* __restrict__ mod_w,
                         const float* __restrict__ mod_b) {
    // ws[tap_local][c][28] : 27 real channels + 1 zero pad (for packed pairs)
    __shared__ __align__(16) float ws[3][CC][28];
    int b = blockIdx.z;
    int h = blockIdx.y * 16 + (threadIdx.x >> 4);
    int w = blockIdx.x * 16 + (threadIdx.x & 15);

    u64 acc[14];
#pragma unroll
    for (int j = 0; j < 14; j++) acc[j] = 0ull;

    for (int tg = 0; tg < 3; ++tg) {           // tap row (dy = tg-1)
        __syncthreads();
        for (int idx = threadIdx.x; idx < 3 * CC * 28; idx += blockDim.x) {
            int tl = idx / (CC * 28);
            int r  = idx % (CC * 28);
            int c  = r / 28;
            int ch = r % 28;
            int t  = tg * 3 + tl;
            float wv = 0.f;
            if (ch < 18)      wv = offset_w[(ch * CC + c) * K2 + t];
            else if (ch < 27) wv = mod_w[((ch - 18) * CC + c) * K2 + t];
            ws[tl][c][ch] = wv;
        }
        __syncthreads();

        int y = h + tg - 1;
        if (y < 0 || y >= HH) continue;
#pragma unroll
        for (int tl = 0; tl < 3; ++tl) {       // tap col (dx = tl-1)
            int xx = w + tl - 1;
            if (xx < 0 || xx >= WW) continue;
            const float4* row4 =
                reinterpret_cast<const float4*>(&g_xT[((b * HH + y) * WW + xx) * CC]);
#pragma unroll 2
            for (int c4 = 0; c4 < CC / 4; c4++) {
                float4 v4 = row4[c4];
                u64 vd0, vd1, vd2, vd3;
                DUP2(vd0, v4.x); DUP2(vd1, v4.y);
                DUP2(vd2, v4.z); DUP2(vd3, v4.w);
                ACCP(vd0, &ws[tl][c4 * 4 + 0][0]);
                ACCP(vd1, &ws[tl][c4 * 4 + 1][0]);
                ACCP(vd2, &ws[tl][c4 * 4 + 2][0]);
                ACCP(vd3, &ws[tl][c4 * 4 + 3][0]);
            }
        }
    }

    int pix = (b * HH + h) * WW + w;
    float* op = &g_off[(size_t)pix * 18];
#pragma unroll
    for (int j = 0; j < 9; j++) {
        op[2 * j]     = LOF(acc[j]) + offset_b[2 * j];
        op[2 * j + 1] = HIF(acc[j]) + offset_b[2 * j + 1];
    }

    float mv[9];
    mv[0] = LOF(acc[9]);  mv[1] = HIF(acc[9]);
    mv[2] = LOF(acc[10]); mv[3] = HIF(acc[10]);
    mv[4] = LOF(acc[11]); mv[5] = HIF(acc[11]);
    mv[6] = LOF(acc[12]); mv[7] = HIF(acc[12]);
    mv[8] = LOF(acc[13]);
    float mm = 0.f;
#pragma unroll
    for (int j = 0; j < 9; j++) {
        float z = mv[j] + mod_b[j];
        mm += 1.f / (1.f + expf(-z));
    }
    g_mm[pix] = mm * (1.f / 9.f);
}

// ---------------- kernel 3: pipelined gather + row-tile f32x2 GEMM -----------
// Block = one image row (128 px) x all 64 outputs. 256 threads.
// Double-buffered ss (samples) and wk (weights): gather tap k+1 overlaps the
// GEMM of tap k; one barrier per tap. GEMM per c: 3 LDS + 8 packs + 16 FMA2.
#define SMEM_MAIN ((2 * CC * OO + 2 * CC * WW) * 4)

__global__ void __launch_bounds__(256, 2) k_main(const float* __restrict__ bias,
                                                 float* __restrict__ out) {
    extern __shared__ __align__(16) float dyn[];
    float* wkb = dyn;                  // [2][CC*OO]  32KB
    float* ssb = dyn + 2 * CC * OO;    // [2][CC*WW]  64KB

    int h = blockIdx.x;
    int b = blockIdx.y;
    int tid = threadIdx.x;

    // gather mapping: 2 threads per pixel (each owns 32 channels)
    int gpix = tid & 127;
    int gc0  = (tid >> 7) * 32;
    const float* offp = &g_off[(size_t)((b * HH + h) * WW + gpix) * 18];

    // GEMM mapping: warp = 8 outputs (broadcast weights), lane = 4 pixels
    int o0 = (tid >> 5) * 8;
    int p0 = (tid & 31) * 4;

    u64 acc[16];
#pragma unroll
    for (int i = 0; i < 16; i++) acc[i] = 0ull;

    auto stage = [&](int k, int buf) {
        // ---- weight slice [c][o] for tap k ----
        {
            const float4* src = reinterpret_cast<const float4*>(&g_w3[k * CC * OO]);
            float4* dst = reinterpret_cast<float4*>(&wkb[buf * CC * OO]);
#pragma unroll
            for (int i = 0; i < CC * OO / 4 / 256; i++)
                dst[tid + i * 256] = src[tid + i * 256];
        }
        // ---- bilinear samples for tap k (32 channels/thread) ----
        float offy = offp[k];
        float offx = offp[9 + k];
        float sy = (float)(h + k / 3 - 1) + offy;
        float sx = (float)(gpix + k % 3 - 1) + offx;
        float fy0 = floorf(sy), fx0 = floorf(sx);
        int iy0 = (int)fy0, ix0 = (int)fx0;
        float ay = sy - fy0, ax = sx - fx0;
        float wy[2] = {1.f - ay, ay};
        float wx[2] = {1.f - ax, ax};
        const ulonglong2* cp[4];
        u64 wtd[4];
#pragma unroll
        for (int q = 0; q < 4; q++) {
            int iy = iy0 + (q >> 1), ix = ix0 + (q & 1);
            bool ok = (iy >= 0 && iy < HH && ix >= 0 && ix < WW);
            float wt = ok ? wy[q >> 1] * wx[q & 1] : 0.f;
            DUP2(wtd[q], wt);
            int iyc = min(max(iy, 0), HH - 1);
            int ixc = min(max(ix, 0), WW - 1);
            cp[q] = reinterpret_cast<const ulonglong2*>(
                &g_xT[((size_t)(b * HH + iyc) * WW + ixc) * CC + gc0]);
        }
        float* ssp = &ssb[buf * CC * WW];
#pragma unroll
        for (int ch = 0; ch < 4; ch++) {       // 4 chunks of 8 channels
            u64 v0 = 0ull, v1 = 0ull, v2 = 0ull, v3 = 0ull;
#pragma unroll
            for (int q = 0; q < 4; q++) {
                ulonglong2 a0 = cp[q][ch * 2];
                ulonglong2 a1 = cp[q][ch * 2 + 1];
                FMA2(v0, wtd[q], a0.x, v0);
                FMA2(v1, wtd[q], a0.y, v1);
                FMA2(v2, wtd[q], a1.x, v2);
                FMA2(v3, wtd[q], a1.y, v3);
            }
            float* sp = ssp + (gc0 + ch * 8) * WW + gpix;
            sp[0 * WW] = LOF(v0); sp[1 * WW] = HIF(v0);
            sp[2 * WW] = LOF(v1); sp[3 * WW] = HIF(v1);
            sp[4 * WW] = LOF(v2); sp[5 * WW] = HIF(v2);
            sp[6 * WW] = LOF(v3); sp[7 * WW] = HIF(v3);
        }
    };

    stage(0, 0);
    __syncthreads();

    for (int k = 0; k < K2; k++) {
        int cur = k & 1;
        if (k < K2 - 1) stage(k + 1, cur ^ 1);   // overlaps GEMM below

        const float* wkp = &wkb[cur * CC * OO];
        const float* ssp = &ssb[cur * CC * WW];
#pragma unroll 4
        for (int c = 0; c < CC; c++) {
            float4 w0 = *reinterpret_cast<const float4*>(&wkp[c * OO + o0]);
            float4 w1 = *reinterpret_cast<const float4*>(&wkp[c * OO + o0 + 4]);
            ulonglong2 s = *reinterpret_cast<const ulonglong2*>(&ssp[c * WW + p0]);
            u64 wd;
            DUP2(wd, w0.x); FMA2(acc[0],  wd, s.x, acc[0]);  FMA2(acc[1],  wd, s.y, acc[1]);
            DUP2(wd, w0.y); FMA2(acc[2],  wd, s.x, acc[2]);  FMA2(acc[3],  wd, s.y, acc[3]);
            DUP2(wd, w0.z); FMA2(acc[4],  wd, s.x, acc[4]);  FMA2(acc[5],  wd, s.y, acc[5]);
            DUP2(wd, w0.w); FMA2(acc[6],  wd, s.x, acc[6]);  FMA2(acc[7],  wd, s.y, acc[7]);
            DUP2(wd, w1.x); FMA2(acc[8],  wd, s.x, acc[8]);  FMA2(acc[9],  wd, s.y, acc[9]);
            DUP2(wd, w1.y); FMA2(acc[10], wd, s.x, acc[10]); FMA2(acc[11], wd, s.y, acc[11]);
            DUP2(wd, w1.z); FMA2(acc[12], wd, s.x, acc[12]); FMA2(acc[13], wd, s.y, acc[13]);
            DUP2(wd, w1.w); FMA2(acc[14], wd, s.x, acc[14]); FMA2(acc[15], wd, s.y, acc[15]);
        }
        __syncthreads();
    }

    // ---- epilogue: * mod_mean + bias, write NCHW ----
    ulonglong2 mm2 = *reinterpret_cast<const ulonglong2*>(
        &g_mm[(size_t)((b * HH + h) * WW) + p0]);
#pragma unroll
    for (int r = 0; r < 8; r++) {
        u64 bd;
        DUP2(bd, bias[o0 + r]);
        u64 t0, t1;
        FMA2(t0, acc[2 * r],     mm2.x, bd);
        FMA2(t1, acc[2 * r + 1], mm2.y, bd);
        ulonglong2 res; res.x = t0; res.y = t1;
        *reinterpret_cast<ulonglong2*>(
            &out[((size_t)(b * OO + o0 + r) * HH + h) * WW + p0]) = res;
    }
}

// ---------------- launch -----------------------------------------------------
extern "C" void kernel_launch(void* const* d_in, const int* in_sizes, int n_in,
                              void* d_out, int out_size) {
    const float* x        = (const float*)d_in[0];
    const float* weight   = (const float*)d_in[1];
    const float* bias     = (const float*)d_in[2];
    const float* offset_w = (const float*)d_in[3];
    const float* offset_b = (const float*)d_in[4];
    const float* mod_w    = (const float*)d_in[5];
    const float* mod_b    = (const float*)d_in[6];
    float* out = (float*)d_out;

    cudaFuncSetAttribute(k_main, cudaFuncAttributeMaxDynamicSharedMemorySize,
                         SMEM_MAIN);

    k_transpose<<<BB * HH, 256>>>(x);
    k_wreorg<<<36, 256>>>(weight);
    k_offmod<<<dim3(WW / 16, HH / 16, BB), 256>>>(offset_w, offset_b, mod_w, mod_b);
    k_main<<<dim3(HH, BB), 256, SMEM_MAIN>>>(bias, out);
}

// round 4
// speedup vs baseline: 1.3301x; 1.3301x over previous
#include <cuda_runtime.h>
#include <math.h>

#define BB 4
#define CC 64
#define HH 128
#define WW 128
#define OO 64
#define KK 3
#define K2 9

#define SS_STRIDE 132   // ss row stride (floats): 16B-aligned, bank-staggered

// ---------------- scratch (device globals; no allocation allowed) ------------
__device__ float g_xT[BB*HH*WW*CC];     // x transposed to (B,H,W,C)   ~16.8MB
__device__ float g_off[BB*HH*WW*18];    // per-pixel packed offsets (9 y, 9 x)
__device__ float g_mm [BB*HH*WW];       // per-pixel modulation mean
__device__ float g_w3 [K2*CC*OO];       // weight reorganized [k][c][o]

// ---------------- kernel 0: NCHW -> NHWC transpose ---------------------------
__global__ void k_transpose(const float* __restrict__ x) {
    int b = blockIdx.x >> 7;        // gridDim.x = B*H = 512
    int h = blockIdx.x & 127;
    __shared__ float tile[CC][WW + 1];
    for (int idx = threadIdx.x; idx < CC * WW; idx += blockDim.x) {
        int c = idx >> 7, w = idx & 127;
        tile[c][w] = x[((b * CC + c) * HH + h) * WW + w];
    }
    __syncthreads();
    for (int idx = threadIdx.x; idx < CC * WW; idx += blockDim.x) {
        int w = idx >> 6, c = idx & 63;
        g_xT[((b * HH + h) * WW + w) * CC + c] = tile[c][w];
    }
}

// ---------------- kernel 1: weight reorg (O,C,3,3) -> [k][c][o] --------------
__global__ void k_wreorg(const float* __restrict__ weight) {
    for (int idx = blockIdx.x * blockDim.x + threadIdx.x; idx < K2 * CC * OO;
         idx += gridDim.x * blockDim.x) {
        int k = idx / (CC * OO);
        int r = idx % (CC * OO);
        int c = r / OO;
        int o = r % OO;
        g_w3[idx] = weight[(o * CC + c) * K2 + k];
    }
}

// ---------------- kernel 2: fused offset(18) + mod(9) 3x3 conv ---------------
// Block = 2 rows x 128 px (thread = pixel). Per 16-channel chunk: stage a
// 4-row x 130-px x 16-ch window of xT in smem (coalesced LDG), plus all 9 taps'
// weights; compute phase is conflict-free LDS + FMA only.
#define XROWS 4
#define XPX   130
#define CHP   17      // channel pad for conflict-free lane-stride-17 LDS
#define XS_FLOATS (XROWS * XPX * CHP)          // 8840
#define WS_FLOATS (K2 * 16 * 28)               // 4032
#define SMEM_OFFMOD ((XS_FLOATS + WS_FLOATS) * 4)

#define ACC27(v, wp) do {                                                      \
    const float4* w4_ = reinterpret_cast<const float4*>(wp);                   \
    float4 q_;                                                                 \
    q_ = w4_[0]; acc[0]+=(v)*q_.x; acc[1]+=(v)*q_.y; acc[2]+=(v)*q_.z; acc[3]+=(v)*q_.w; \
    q_ = w4_[1]; acc[4]+=(v)*q_.x; acc[5]+=(v)*q_.y; acc[6]+=(v)*q_.z; acc[7]+=(v)*q_.w; \
    q_ = w4_[2]; acc[8]+=(v)*q_.x; acc[9]+=(v)*q_.y; acc[10]+=(v)*q_.z; acc[11]+=(v)*q_.w; \
    q_ = w4_[3]; acc[12]+=(v)*q_.x; acc[13]+=(v)*q_.y; acc[14]+=(v)*q_.z; acc[15]+=(v)*q_.w; \
    q_ = w4_[4]; acc[16]+=(v)*q_.x; acc[17]+=(v)*q_.y; acc[18]+=(v)*q_.z; acc[19]+=(v)*q_.w; \
    q_ = w4_[5]; acc[20]+=(v)*q_.x; acc[21]+=(v)*q_.y; acc[22]+=(v)*q_.z; acc[23]+=(v)*q_.w; \
    q_ = w4_[6]; acc[24]+=(v)*q_.x; acc[25]+=(v)*q_.y; acc[26]+=(v)*q_.z;     \
} while (0)

__global__ void __launch_bounds__(256, 2) k_offmod(const float* __restrict__ offset_w,
                                                   const float* __restrict__ offset_b,
                                                   const float* __restrict__ mod_w,
                                                   const float* __restrict__ mod_b) {
    extern __shared__ __align__(16) float dynsm[];
    float* xs = dynsm;                  // [4][130][17]
    float* ws = dynsm + XS_FLOATS;      // [9][16][28]

    int b  = blockIdx.y;
    int r0 = blockIdx.x * 2;
    int tid = threadIdx.x;
    int p = tid & 127;                  // pixel column
    int r = tid >> 7;                   // pixel row within block (0/1)

    float acc[27];
#pragma unroll
    for (int j = 0; j < 27; j++) acc[j] = 0.f;

    for (int chunk = 0; chunk < 4; chunk++) {
        int ch0 = chunk * 16;
        __syncthreads();

        // stage weights for this channel chunk, all 9 taps
        for (int i = tid; i < WS_FLOATS; i += 256) {
            int t   = i / 448;
            int rem = i % 448;
            int c   = rem / 28;
            int ch  = rem % 28;
            float wv = 0.f;
            if (ch < 18)      wv = offset_w[(ch * CC + ch0 + c) * K2 + t];
            else if (ch < 27) wv = mod_w[((ch - 18) * CC + ch0 + c) * K2 + t];
            ws[i] = wv;
        }

        // stage x window: 4 rows x 130 px x 16 ch (float4-chunked LDG)
        for (int i = tid; i < XROWS * XPX * 4; i += 256) {
            int c4  = i & 3;
            int rem = i >> 2;           // row*130 + px
            int px  = rem % XPX;
            int row = rem / XPX;
            int y = r0 - 1 + row;
            int x = px - 1;
            float4 v = make_float4(0.f, 0.f, 0.f, 0.f);
            if (y >= 0 && y < HH && x >= 0 && x < WW)
                v = *reinterpret_cast<const float4*>(
                    &g_xT[((size_t)(b * HH + y) * WW + x) * CC + ch0 + c4 * 4]);
            float* d = &xs[(row * XPX + px) * CHP + c4 * 4];
            d[0] = v.x; d[1] = v.y; d[2] = v.z; d[3] = v.w;
        }
        __syncthreads();

        // compute: 9 taps x 16 channels
#pragma unroll
        for (int t = 0; t < K2; t++) {
            int ty = t / 3, tx = t % 3;
            const float* xrow = &xs[((r + ty) * XPX + (p + tx)) * CHP];
            const float* wsb  = &ws[t * 16 * 28];
#pragma unroll
            for (int c = 0; c < 16; c++) {
                float v = xrow[c];
                ACC27(v, &wsb[c * 28]);
            }
        }
    }

    int pix = (b * HH + r0 + r) * WW + p;
    float* op = &g_off[(size_t)pix * 18];
#pragma unroll
    for (int j = 0; j < 18; j++) op[j] = acc[j] + offset_b[j];

    float mm = 0.f;
#pragma unroll
    for (int j = 0; j < 9; j++) {
        float z = acc[18 + j] + mod_b[j];
        mm += 1.f / (1.f + expf(-z));
    }
    g_mm[pix] = mm * (1.f / 9.f);
}

// ---------------- kernel 3: coalesced gather + row-tile GEMM -----------------
// Block = one image row (128 px) x all 64 outputs, 256 threads.
// Gather: warp = 2 pixels x 16 lanes; each lane loads one float4 per corner
//   -> 4 wavefronts per corner-LDG (vs 32 for thread-per-pixel).
// GEMM: warp = 8 outputs (broadcast weights), lane = 4 pixels, 32 acc/thread.
#define SMEM_MAIN ((CC * OO + CC * SS_STRIDE) * 4)

__global__ void __launch_bounds__(256, 3) k_main(const float* __restrict__ bias,
                                                 float* __restrict__ out) {
    extern __shared__ __align__(16) float dyn[];
    float* wk = dyn;                    // [CC][OO]        16KB
    float* ss = dyn + CC * OO;          // [CC][SS_STRIDE] 33KB

    int h = blockIdx.x;
    int b = blockIdx.y;
    int tid  = threadIdx.x;
    int warp = tid >> 5;
    int lane = tid & 31;
    int hw = lane >> 4;                 // which pixel of the pair
    int f4 = lane & 15;                 // which float4 (4 channels) of 64 ch
    int trot = f4 & 3;                  // STS bank-rotation amount

    // GEMM mapping
    int o0 = warp * 8;
    int p0 = lane * 4;

    float acc[32];
#pragma unroll
    for (int i = 0; i < 32; i++) acc[i] = 0.f;

    for (int k = 0; k < K2; k++) {
        __syncthreads();   // previous GEMM done reading wk/ss

        // ---- stage weight slice [c][o] (coalesced float4 copy) ----
        {
            const float4* src = reinterpret_cast<const float4*>(&g_w3[k * CC * OO]);
            float4* dst = reinterpret_cast<float4*>(wk);
#pragma unroll
            for (int i = 0; i < CC * OO / 4 / 256; i++)
                dst[tid + i * 256] = src[tid + i * 256];
        }

        // ---- gather: 8 passes, 2 pixels per warp per pass ----
        int ky = k / 3 - 1, kx = k % 3 - 1;
#pragma unroll
        for (int pass = 0; pass < 8; pass++) {
            int pix = pass * 16 + warp * 2 + hw;
            const float* offp = &g_off[(size_t)((b * HH + h) * WW + pix) * 18];
            float sy = (float)(h + ky) + offp[k];
            float sx = (float)(pix + kx) + offp[9 + k];
            float fy0 = floorf(sy), fx0 = floorf(sx);
            int iy0 = (int)fy0, ix0 = (int)fx0;
            float ay = sy - fy0, ax = sx - fx0;
            float wy[2] = {1.f - ay, ay};
            float wx[2] = {1.f - ax, ax};

            float v0 = 0.f, v1 = 0.f, v2 = 0.f, v3 = 0.f;
#pragma unroll
            for (int q = 0; q < 4; q++) {
                int iy = iy0 + (q >> 1), ix = ix0 + (q & 1);
                bool ok = (iy >= 0 && iy < HH && ix >= 0 && ix < WW);
                float wt = ok ? wy[q >> 1] * wx[q & 1] : 0.f;
                int iyc = min(max(iy, 0), HH - 1);
                int ixc = min(max(ix, 0), WW - 1);
                float4 a = reinterpret_cast<const float4*>(
                    &g_xT[((size_t)(b * HH + iyc) * WW + ixc) * CC])[f4];
                v0 = fmaf(wt, a.x, v0);
                v1 = fmaf(wt, a.y, v1);
                v2 = fmaf(wt, a.z, v2);
                v3 = fmaf(wt, a.w, v3);
            }

            // rotated scalar stores: channel order (i+trot)&3 per lane
            // -> 8 distinct banks across the warp instead of 4
            float* sp = &ss[(f4 * 4) * SS_STRIDE + pix];
#pragma unroll
            for (int i = 0; i < 4; i++) {
                int j = (i + trot) & 3;
                float val = (j & 2) ? ((j & 1) ? v3 : v2)
                                    : ((j & 1) ? v1 : v0);
                sp[j * SS_STRIDE] = val;
            }
        }

        __syncthreads();

        // ---- register-tiled GEMM: acc[o][p] += wk[c][o] * ss[c][p] ----
#pragma unroll 4
        for (int c = 0; c < CC; c++) {
            float4 w0 = *reinterpret_cast<const float4*>(&wk[c * OO + o0]);
            float4 w1 = *reinterpret_cast<const float4*>(&wk[c * OO + o0 + 4]);
            float4 s  = *reinterpret_cast<const float4*>(&ss[c * SS_STRIDE + p0]);
            acc[0]  += w0.x * s.x; acc[1]  += w0.x * s.y; acc[2]  += w0.x * s.z; acc[3]  += w0.x * s.w;
            acc[4]  += w0.y * s.x; acc[5]  += w0.y * s.y; acc[6]  += w0.y * s.z; acc[7]  += w0.y * s.w;
            acc[8]  += w0.z * s.x; acc[9]  += w0.z * s.y; acc[10] += w0.z * s.z; acc[11] += w0.z * s.w;
            acc[12] += w0.w * s.x; acc[13] += w0.w * s.y; acc[14] += w0.w * s.z; acc[15] += w0.w * s.w;
            acc[16] += w1.x * s.x; acc[17] += w1.x * s.y; acc[18] += w1.x * s.z; acc[19] += w1.x * s.w;
            acc[20] += w1.y * s.x; acc[21] += w1.y * s.y; acc[22] += w1.y * s.z; acc[23] += w1.y * s.w;
            acc[24] += w1.z * s.x; acc[25] += w1.z * s.y; acc[26] += w1.z * s.z; acc[27] += w1.z * s.w;
            acc[28] += w1.w * s.x; acc[29] += w1.w * s.y; acc[30] += w1.w * s.z; acc[31] += w1.w * s.w;
        }
    }

    // ---- epilogue: * mod_mean + bias, write NCHW ----
    float4 mmv = *reinterpret_cast<const float4*>(
        &g_mm[(size_t)((b * HH + h) * WW) + p0]);
#pragma unroll
    for (int r = 0; r < 8; r++) {
        float bo = bias[o0 + r];
        float4 res;
        res.x = acc[r * 4 + 0] * mmv.x + bo;
        res.y = acc[r * 4 + 1] * mmv.y + bo;
        res.z = acc[r * 4 + 2] * mmv.z + bo;
        res.w = acc[r * 4 + 3] * mmv.w + bo;
        *reinterpret_cast<float4*>(
            &out[((size_t)(b * OO + o0 + r) * HH + h) * WW + p0]) = res;
    }
}

// ---------------- launch -----------------------------------------------------
extern "C" void kernel_launch(void* const* d_in, const int* in_sizes, int n_in,
                              void* d_out, int out_size) {
    const float* x        = (const float*)d_in[0];
    const float* weight   = (const float*)d_in[1];
    const float* bias     = (const float*)d_in[2];
    const float* offset_w = (const float*)d_in[3];
    const float* offset_b = (const float*)d_in[4];
    const float* mod_w    = (const float*)d_in[5];
    const float* mod_b    = (const float*)d_in[6];
    float* out = (float*)d_out;

    cudaFuncSetAttribute(k_main, cudaFuncAttributeMaxDynamicSharedMemorySize,
                         SMEM_MAIN);
    cudaFuncSetAttribute(k_offmod, cudaFuncAttributeMaxDynamicSharedMemorySize,
                         SMEM_OFFMOD);

    k_transpose<<<BB * HH, 256>>>(x);
    k_wreorg<<<36, 256>>>(weight);
    k_offmod<<<dim3(HH / 2, BB), 256, SMEM_OFFMOD>>>(offset_w, offset_b,
                                                     mod_w, mod_b);
    k_main<<<dim3(HH, BB), 256, SMEM_MAIN>>>(bias, out);
}